// round 1
// baseline (speedup 1.0000x reference)
#include <cuda_runtime.h>
#include <cstdint>
#include <math.h>

// Problem constants
#define N_TOK 8192
#define DIM   1024
#define HID   2048
#define OUTD  1024
#define NEXP  8
#define TOPK  2
#define EPSBN 1e-5f

// GEMM tiling
#define BM 128
#define BN 128
#define BK 16

#define ROWS_MAX (N_TOK*TOPK + NEXP*BM)   // 17408 (per-expert 128-padded)

// ---------------- static device scratch (no allocations allowed) ----------------
__device__ float g_bufA[(size_t)ROWS_MAX * HID];   // ~142.6 MB
__device__ float g_bufB[(size_t)ROWS_MAX * HID];   // ~142.6 MB
__device__ int   g_cnt[NEXP];
__device__ int   g_off[NEXP + 1];
__device__ int   g_fill[NEXP];
__device__ int   g_tok2[N_TOK * TOPK];
__device__ float g_w2[N_TOK * TOPK];
__device__ int   g_rowtok[ROWS_MAX];
__device__ float g_roww[ROWS_MAX];

// ---------------- init: reset counters + row map (graph replay safe) ------------
__global__ void k_init() {
    int i = blockIdx.x * blockDim.x + threadIdx.x;
    if (i < ROWS_MAX) g_rowtok[i] = -1;
    if (i < NEXP)     g_cnt[i] = 0;
}

// ---------------- gate: softmax + top-2 + renormalize, count per expert ---------
// one warp per token; 256 threads = 8 tokens/block
__global__ void k_gate(const float* __restrict__ x, const float* __restrict__ Wg) {
    int warp = threadIdx.x >> 5;
    int lane = threadIdx.x & 31;
    int t = blockIdx.x * 8 + warp;
    if (t >= N_TOK) return;

    const float* xr = x + (size_t)t * DIM;
    float acc[NEXP];
#pragma unroll
    for (int e = 0; e < NEXP; e++) acc[e] = 0.f;

    for (int d = lane; d < DIM; d += 32) {
        float xv = xr[d];
#pragma unroll
        for (int e = 0; e < NEXP; e++)
            acc[e] = fmaf(xv, Wg[e * DIM + d], acc[e]);
    }
#pragma unroll
    for (int e = 0; e < NEXP; e++) {
#pragma unroll
        for (int s = 16; s > 0; s >>= 1)
            acc[e] += __shfl_xor_sync(0xffffffffu, acc[e], s);
    }
    if (lane == 0) {
        float mx = acc[0];
#pragma unroll
        for (int e = 1; e < NEXP; e++) mx = fmaxf(mx, acc[e]);
        float p[NEXP], sum = 0.f;
#pragma unroll
        for (int e = 0; e < NEXP; e++) { p[e] = expf(acc[e] - mx); sum += p[e]; }
        float inv = 1.f / sum;
#pragma unroll
        for (int e = 0; e < NEXP; e++) p[e] *= inv;

        int i0 = 0;
#pragma unroll
        for (int e = 1; e < NEXP; e++) if (p[e] > p[i0]) i0 = e;
        int i1 = (i0 == 0) ? 1 : 0;
#pragma unroll
        for (int e = 0; e < NEXP; e++) if (e != i0 && p[e] > p[i1]) i1 = e;

        float den = p[i0] + p[i1] + 1e-20f;
        float w0 = p[i0] / den;
        float w1 = p[i1] / den;

        g_tok2[2 * t + 0] = i0; g_w2[2 * t + 0] = w0;
        g_tok2[2 * t + 1] = i1; g_w2[2 * t + 1] = w1;
        atomicAdd(&g_cnt[i0], 1);
        atomicAdd(&g_cnt[i1], 1);
    }
}

// ---------------- offsets: 128-aligned exclusive prefix over counts -------------
__global__ void k_offsets() {
    if (threadIdx.x == 0) {
        int o = 0;
        for (int e = 0; e < NEXP; e++) {
            g_off[e] = o;
            o += ((g_cnt[e] + BM - 1) / BM) * BM;
        }
        g_off[NEXP] = o;
    }
    if (threadIdx.x < NEXP) g_fill[threadIdx.x] = 0;
}

// ---------------- scatter tokens into compacted per-expert row list -------------
__global__ void k_scatter() {
    int t = blockIdx.x * blockDim.x + threadIdx.x;
    if (t >= N_TOK) return;
#pragma unroll
    for (int s = 0; s < TOPK; s++) {
        int e = g_tok2[2 * t + s];
        int pos = g_off[e] + atomicAdd(&g_fill[e], 1);
        g_rowtok[pos] = t;
        g_roww[pos]  = g_w2[2 * t + s];
    }
}

// ---------------- fused GEMM:  C = epi(A @ W^T + b) -----------------------------
// A rows: direct (r) or gathered via g_rowtok[r] (GATHER).
// EPI 0: relu + batchnorm   -> out[r*Hout + n]
// EPI 1: sigmoid            -> out[r*Hout + n]
// EPI 2: sigmoid * w, atomicAdd -> out[tok*Hout + n]
// off != nullptr => grouped-expert mode: per-tile expert id from g_off scan.
template<int EPI, bool GATHER>
__global__ __launch_bounds__(256, 2)
void gemm_fused(const float* __restrict__ X,
                const float* __restrict__ Wb,
                const float* __restrict__ biasb,
                const float* __restrict__ gb, const float* __restrict__ beb,
                const float* __restrict__ mb, const float* __restrict__ vb,
                float* __restrict__ out,
                int Kd, int Hout,
                long wstride, int pstride,
                const int* __restrict__ off)
{
    __shared__ float As[BK][BM + 4];
    __shared__ float Bs[BK][BN + 4];

    int tileStart = blockIdx.y * BM;
    int e = 0;
    if (off) {
        int total = off[NEXP];
        if (tileStart >= total) return;
        while (e < NEXP - 1 && off[e + 1] <= tileStart) e++;
    }
    const float* W    = Wb    + (size_t)e * (size_t)wstride;
    const float* bias = biasb + (size_t)e * (size_t)pstride;

    int tid  = threadIdx.x;
    int tm   = tid >> 4;          // 0..15
    int tn   = tid & 15;          // 0..15
    int rbase = tileStart;
    int nbase = blockIdx.x * BN;

    // global load assignment: 2 float4 each for A and W
    int row0 = tid >> 2;          // 0..63
    int row1 = row0 + 64;         // 64..127
    int kq   = (tid & 3) * 4;     // 0,4,8,12

    const float* aptr0;
    const float* aptr1;
    bool ok0 = true, ok1 = true;
    if (GATHER) {
        int t0 = g_rowtok[rbase + row0];
        int t1 = g_rowtok[rbase + row1];
        ok0 = (t0 >= 0); ok1 = (t1 >= 0);
        aptr0 = X + (size_t)(ok0 ? t0 : 0) * Kd;
        aptr1 = X + (size_t)(ok1 ? t1 : 0) * Kd;
    } else {
        aptr0 = X + (size_t)(rbase + row0) * Kd;
        aptr1 = X + (size_t)(rbase + row1) * Kd;
    }
    const float* bptr0 = W + (size_t)(nbase + row0) * Kd;
    const float* bptr1 = W + (size_t)(nbase + row1) * Kd;

    float acc[8][8];
#pragma unroll
    for (int i = 0; i < 8; i++)
#pragma unroll
        for (int j = 0; j < 8; j++) acc[i][j] = 0.f;

    for (int k0 = 0; k0 < Kd; k0 += BK) {
        float4 z4 = make_float4(0.f, 0.f, 0.f, 0.f);
        float4 a0 = z4, a1 = z4;
        if (!GATHER || ok0) a0 = *(const float4*)(aptr0 + k0 + kq);
        if (!GATHER || ok1) a1 = *(const float4*)(aptr1 + k0 + kq);
        float4 b0 = *(const float4*)(bptr0 + k0 + kq);
        float4 b1 = *(const float4*)(bptr1 + k0 + kq);

        __syncthreads();
        As[kq + 0][row0] = a0.x; As[kq + 1][row0] = a0.y;
        As[kq + 2][row0] = a0.z; As[kq + 3][row0] = a0.w;
        As[kq + 0][row1] = a1.x; As[kq + 1][row1] = a1.y;
        As[kq + 2][row1] = a1.z; As[kq + 3][row1] = a1.w;
        Bs[kq + 0][row0] = b0.x; Bs[kq + 1][row0] = b0.y;
        Bs[kq + 2][row0] = b0.z; Bs[kq + 3][row0] = b0.w;
        Bs[kq + 0][row1] = b1.x; Bs[kq + 1][row1] = b1.y;
        Bs[kq + 2][row1] = b1.z; Bs[kq + 3][row1] = b1.w;
        __syncthreads();

#pragma unroll
        for (int kk = 0; kk < BK; kk++) {
            float av[8], bv[8];
            *(float4*)&av[0] = *(const float4*)&As[kk][tm * 8];
            *(float4*)&av[4] = *(const float4*)&As[kk][tm * 8 + 4];
            *(float4*)&bv[0] = *(const float4*)&Bs[kk][tn * 8];
            *(float4*)&bv[4] = *(const float4*)&Bs[kk][tn * 8 + 4];
#pragma unroll
            for (int i = 0; i < 8; i++)
#pragma unroll
                for (int j = 0; j < 8; j++)
                    acc[i][j] = fmaf(av[i], bv[j], acc[i][j]);
        }
    }

    int ncol = nbase + tn * 8;

    if (EPI == 0) {
        const float* gp  = gb  + (size_t)e * (size_t)pstride;
        const float* bep = beb + (size_t)e * (size_t)pstride;
        const float* mp  = mb  + (size_t)e * (size_t)pstride;
        const float* vp  = vb  + (size_t)e * (size_t)pstride;
        float bs[8], sc[8], sh[8];
#pragma unroll
        for (int j = 0; j < 8; j++) {
            int n = ncol + j;
            bs[j] = bias[n];
            float s = gp[n] * rsqrtf(vp[n] + EPSBN);
            sc[j] = s;
            sh[j] = fmaf(-mp[n], s, bep[n]);
        }
#pragma unroll
        for (int i = 0; i < 8; i++) {
            int r = rbase + tm * 8 + i;
            float* orow = out + (size_t)r * Hout + ncol;
            float o[8];
#pragma unroll
            for (int j = 0; j < 8; j++) {
                float z = fmaxf(acc[i][j] + bs[j], 0.f);
                o[j] = fmaf(z, sc[j], sh[j]);
            }
            *(float4*)(orow)     = *(float4*)&o[0];
            *(float4*)(orow + 4) = *(float4*)&o[4];
        }
    } else if (EPI == 1) {
        float bs[8];
#pragma unroll
        for (int j = 0; j < 8; j++) bs[j] = bias[ncol + j];
#pragma unroll
        for (int i = 0; i < 8; i++) {
            int r = rbase + tm * 8 + i;
            float* orow = out + (size_t)r * Hout + ncol;
            float o[8];
#pragma unroll
            for (int j = 0; j < 8; j++) {
                float z = acc[i][j] + bs[j];
                o[j] = 1.f / (1.f + expf(-z));
            }
            *(float4*)(orow)     = *(float4*)&o[0];
            *(float4*)(orow + 4) = *(float4*)&o[4];
        }
    } else { // EPI == 2: weighted sigmoid, scatter-add to token rows
        float bs[8];
#pragma unroll
        for (int j = 0; j < 8; j++) bs[j] = bias[ncol + j];
#pragma unroll
        for (int i = 0; i < 8; i++) {
            int r = rbase + tm * 8 + i;
            int tok = g_rowtok[r];
            if (tok < 0) continue;
            float w = g_roww[r];
            float* orow = out + (size_t)tok * Hout + ncol;
#pragma unroll
            for (int j = 0; j < 8; j++) {
                float z = acc[i][j] + bs[j];
                float s = 1.f / (1.f + expf(-z));
                atomicAdd(&orow[j], w * s);
            }
        }
    }
}

// ---------------- launch ----------------
extern "C" void kernel_launch(void* const* d_in, const int* in_sizes, int n_in,
                              void* d_out, int out_size) {
    (void)in_sizes; (void)n_in; (void)out_size;

    const float* x   = (const float*)d_in[0];
    const float* Wg  = (const float*)d_in[1];
    const float* W1  = (const float*)d_in[2];
    const float* b1  = (const float*)d_in[3];
    const float* g1  = (const float*)d_in[4];
    const float* be1 = (const float*)d_in[5];
    const float* m1  = (const float*)d_in[6];
    const float* v1  = (const float*)d_in[7];
    const float* W2  = (const float*)d_in[8];
    const float* b2  = (const float*)d_in[9];
    const float* g2  = (const float*)d_in[10];
    const float* be2 = (const float*)d_in[11];
    const float* m2  = (const float*)d_in[12];
    const float* v2  = (const float*)d_in[13];
    const float* W3  = (const float*)d_in[14];
    const float* b3  = (const float*)d_in[15];
    const float* sW1 = (const float*)d_in[16];
    const float* sb1 = (const float*)d_in[17];
    const float* sg1 = (const float*)d_in[18];
    const float* sbe1= (const float*)d_in[19];
    const float* sm1 = (const float*)d_in[20];
    const float* sv1 = (const float*)d_in[21];
    const float* sW2 = (const float*)d_in[22];
    const float* sb2 = (const float*)d_in[23];
    const float* sg2 = (const float*)d_in[24];
    const float* sbe2= (const float*)d_in[25];
    const float* sm2 = (const float*)d_in[26];
    const float* sv2 = (const float*)d_in[27];
    const float* sW3 = (const float*)d_in[28];
    const float* sb3 = (const float*)d_in[29];
    float* out = (float*)d_out;

    float* bufA; float* bufB; int* off;
    cudaGetSymbolAddress((void**)&bufA, g_bufA);
    cudaGetSymbolAddress((void**)&bufB, g_bufB);
    cudaGetSymbolAddress((void**)&off,  g_off);

    // routing
    k_init<<<(ROWS_MAX + 255) / 256, 256>>>();
    k_gate<<<N_TOK / 8, 256>>>(x, Wg);
    k_offsets<<<1, 32>>>();
    k_scatter<<<(N_TOK + 255) / 256, 256>>>();

    // shared expert: x -> bufA -> bufB -> out (plain store, initializes d_out)
    gemm_fused<0, false><<<dim3(HID / BN, N_TOK / BM), 256>>>(
        x, sW1, sb1, sg1, sbe1, sm1, sv1, bufA, DIM, HID, 0, 0, nullptr);
    gemm_fused<0, false><<<dim3(HID / BN, N_TOK / BM), 256>>>(
        bufA, sW2, sb2, sg2, sbe2, sm2, sv2, bufB, HID, HID, 0, 0, nullptr);
    gemm_fused<1, false><<<dim3(OUTD / BN, N_TOK / BM), 256>>>(
        bufB, sW3, sb3, nullptr, nullptr, nullptr, nullptr, out, HID, OUTD, 0, 0, nullptr);

    // routed experts (top-2 sparse, compacted rows): gather -> bufA -> bufB -> out (+=)
    gemm_fused<0, true><<<dim3(HID / BN, ROWS_MAX / BM), 256>>>(
        x, W1, b1, g1, be1, m1, v1, bufA, DIM, HID,
        (long)HID * DIM, HID, off);
    gemm_fused<0, false><<<dim3(HID / BN, ROWS_MAX / BM), 256>>>(
        bufA, W2, b2, g2, be2, m2, v2, bufB, HID, HID,
        (long)HID * HID, HID, off);
    gemm_fused<2, false><<<dim3(OUTD / BN, ROWS_MAX / BM), 256>>>(
        bufB, W3, b3, nullptr, nullptr, nullptr, nullptr, out, HID, OUTD,
        (long)OUTD * HID, OUTD, off);
}

// round 4
// speedup vs baseline: 3.0693x; 3.0693x over previous
#include <cuda_runtime.h>
#include <cstdint>
#include <math.h>

// ---------------- problem constants ----------------
#define N_TOK 8192
#define DIM   1024
#define HID   2048
#define OUTD  1024
#define NEXP  8
#define TOPK  2
#define EPSBN 1e-5f

// ---------------- GEMM tiling ----------------
#define BM 128
#define BN 128
#define BKC 32               // K elements per pipeline stage

#define ROWS_MAX (N_TOK*TOPK + NEXP*BM)   // 17408

// smem: 2 stages of (A:128x36 + B:128x36) floats, then 3x128 epilogue params
#define APAD    36
#define STAGE_F (128*APAD*2)       // 9216 floats per stage
#define PAR_F   (2*STAGE_F)        // 18432
#define SMEM_FLOATS (PAR_F + 384)
#define SMEM_BYTES  (SMEM_FLOATS*4)   // 75264 bytes

// ---------------- static device scratch ----------------
__device__ float g_bufA[(size_t)ROWS_MAX * HID];
__device__ float g_bufB[(size_t)ROWS_MAX * HID];
__device__ int   g_cnt[NEXP];
__device__ int   g_off[NEXP + 1];
__device__ int   g_fill[NEXP];
__device__ int   g_tok2[N_TOK * TOPK];
__device__ float g_w2[N_TOK * TOPK];
__device__ int   g_rowtok[ROWS_MAX];
__device__ float g_roww[ROWS_MAX];

// ---------------- helpers (all family-agnostic sm_80+ PTX) ----------------
__device__ __forceinline__ uint32_t smem_u32(const void* p) {
    uint32_t a;
    asm("{ .reg .u64 t; cvta.to.shared.u64 t, %1; cvt.u32.u64 %0, t; }" : "=r"(a) : "l"(p));
    return a;
}
__device__ __forceinline__ void cp16(uint32_t dst, const void* src, int szbytes) {
    asm volatile("cp.async.cg.shared.global [%0], [%1], 16, %2;"
                 :: "r"(dst), "l"(src), "r"(szbytes) : "memory");
}
template<int N> __device__ __forceinline__ void cp_wait() {
    asm volatile("cp.async.wait_group %0;" :: "n"(N) : "memory");
}
__device__ __forceinline__ void cp_commit() {
    asm volatile("cp.async.commit_group;" ::: "memory");
}
__device__ __forceinline__ uint32_t f2tf(float f) {
    uint32_t r;
    asm("cvt.rna.tf32.f32 %0, %1;" : "=r"(r) : "f"(f));
    return r;
}
__device__ __forceinline__ void mma_tf32(float* c, const uint32_t* a, const uint32_t* b) {
    asm volatile("mma.sync.aligned.m16n8k8.row.col.f32.tf32.tf32.f32 "
                 "{%0,%1,%2,%3}, {%4,%5,%6,%7}, {%8,%9}, {%0,%1,%2,%3};"
                 : "+f"(c[0]), "+f"(c[1]), "+f"(c[2]), "+f"(c[3])
                 : "r"(a[0]), "r"(a[1]), "r"(a[2]), "r"(a[3]),
                   "r"(b[0]), "r"(b[1]));
}

// ---------------- routing kernels ----------------
__global__ void k_init() {
    int i = blockIdx.x * blockDim.x + threadIdx.x;
    if (i < ROWS_MAX) g_rowtok[i] = -1;
    if (i < NEXP)     g_cnt[i] = 0;
}

__global__ void k_gate(const float* __restrict__ x, const float* __restrict__ Wg) {
    int warp = threadIdx.x >> 5;
    int lane = threadIdx.x & 31;
    int t = blockIdx.x * 8 + warp;
    if (t >= N_TOK) return;
    const float* xr = x + (size_t)t * DIM;
    float acc[NEXP];
#pragma unroll
    for (int e = 0; e < NEXP; e++) acc[e] = 0.f;
    for (int d = lane; d < DIM; d += 32) {
        float xv = xr[d];
#pragma unroll
        for (int e = 0; e < NEXP; e++) acc[e] = fmaf(xv, Wg[e * DIM + d], acc[e]);
    }
#pragma unroll
    for (int e = 0; e < NEXP; e++)
#pragma unroll
        for (int s = 16; s > 0; s >>= 1) acc[e] += __shfl_xor_sync(0xffffffffu, acc[e], s);
    if (lane == 0) {
        float mx = acc[0];
#pragma unroll
        for (int e = 1; e < NEXP; e++) mx = fmaxf(mx, acc[e]);
        float p[NEXP], sum = 0.f;
#pragma unroll
        for (int e = 0; e < NEXP; e++) { p[e] = expf(acc[e] - mx); sum += p[e]; }
        float inv = 1.f / sum;
#pragma unroll
        for (int e = 0; e < NEXP; e++) p[e] *= inv;
        int i0 = 0;
#pragma unroll
        for (int e = 1; e < NEXP; e++) if (p[e] > p[i0]) i0 = e;
        int i1 = (i0 == 0) ? 1 : 0;
#pragma unroll
        for (int e = 0; e < NEXP; e++) if (e != i0 && p[e] > p[i1]) i1 = e;
        float den = p[i0] + p[i1] + 1e-20f;
        g_tok2[2 * t + 0] = i0; g_w2[2 * t + 0] = p[i0] / den;
        g_tok2[2 * t + 1] = i1; g_w2[2 * t + 1] = p[i1] / den;
        atomicAdd(&g_cnt[i0], 1);
        atomicAdd(&g_cnt[i1], 1);
    }
}

__global__ void k_offsets() {
    if (threadIdx.x == 0) {
        int o = 0;
        for (int e = 0; e < NEXP; e++) { g_off[e] = o; o += ((g_cnt[e] + BM - 1) / BM) * BM; }
        g_off[NEXP] = o;
    }
    if (threadIdx.x < NEXP) g_fill[threadIdx.x] = 0;
}

__global__ void k_scatter() {
    int t = blockIdx.x * blockDim.x + threadIdx.x;
    if (t >= N_TOK) return;
#pragma unroll
    for (int s = 0; s < TOPK; s++) {
        int e = g_tok2[2 * t + s];
        int pos = g_off[e] + atomicAdd(&g_fill[e], 1);
        g_rowtok[pos] = t;
        g_roww[pos]  = g_w2[2 * t + s];
    }
}

// ---------------- tf32 mma.sync fused GEMM ----------------
// C[128,128] = epi(A @ W^T + b).  2-stage cp.async pipeline, K-chunk 32.
// 8 warps, warp tile 64x32 (4 m16-tiles x 4 n8-tiles), m16n8k8 tf32 HMMA.
// EPI 0: relu+BN store   EPI 1: sigmoid store   EPI 2: w*sigmoid atomicAdd scatter
template<int EPI, bool GATHER>
__global__ void __launch_bounds__(256, 2)
gemm_tc(const float* __restrict__ X,
        const float* __restrict__ Wb,
        const float* __restrict__ biasb,
        const float* __restrict__ gb, const float* __restrict__ beb,
        const float* __restrict__ mb, const float* __restrict__ vb,
        float* __restrict__ out,
        int Kd, int Hout,
        long wstride, int pstride,
        const int* __restrict__ off)
{
    extern __shared__ float smf[];
    int tid = threadIdx.x;
    int wid = tid >> 5;
    int lid = tid & 31;

    int tileStart = blockIdx.y * BM;
    int e = 0;
    if (off) {
        int total = off[NEXP];
        if (tileStart >= total) return;
        while (e < NEXP - 1 && off[e + 1] <= tileStart) e++;
    }
    const float* W    = Wb    + (size_t)e * (size_t)wstride;
    const float* bias = biasb + (size_t)e * (size_t)pstride;
    int nbase = blockIdx.x * BN;

    // epilogue params
    float* par_b  = smf + PAR_F;
    float* par_sc = par_b + 128;
    float* par_sh = par_b + 256;
    if (tid < 128) {
        int n = nbase + tid;
        par_b[tid] = bias[n];
        if (EPI == 0) {
            size_t pe = (size_t)e * (size_t)pstride + n;
            float s = gb[pe] * rsqrtf(vb[pe] + EPSBN);
            par_sc[tid] = s;
            par_sh[tid] = fmaf(-mb[pe], s, beb[pe]);
        }
    }

    // global->smem load mapping: 256 threads, each 4 rows x 1 float4 per matrix
    int lrow = tid >> 3;            // 0..31
    int lcol = (tid & 7) * 4;       // 0..28
    const float* asrc[4]; int asz[4];
    const float* bsrc[4];
#pragma unroll
    for (int i = 0; i < 4; i++) {
        int r = lrow + 32 * i;
        if (GATHER) {
            int tok = g_rowtok[tileStart + r];
            asrc[i] = X + (size_t)(tok >= 0 ? tok : 0) * Kd + lcol;
            asz[i]  = tok >= 0 ? 16 : 0;
        } else {
            asrc[i] = X + (size_t)(tileStart + r) * Kd + lcol;
            asz[i]  = 16;
        }
        bsrc[i] = W + (size_t)(nbase + r) * Kd + lcol;
    }
    uint32_t sb = smem_u32(smf);
    uint32_t adst[4], bdst[4];
#pragma unroll
    for (int i = 0; i < 4; i++) {
        int r = lrow + 32 * i;
        adst[i] = sb + (uint32_t)(r * APAD + lcol) * 4u;
        bdst[i] = sb + (uint32_t)((128 + r) * APAD + lcol) * 4u;
    }

    float acc[16][4];
#pragma unroll
    for (int i = 0; i < 16; i++)
#pragma unroll
        for (int j = 0; j < 4; j++) acc[i][j] = 0.f;

    int warpM = wid & 1;           // 0..1 -> 64 rows
    int warpN = wid >> 1;          // 0..3 -> 32 cols
    int g = lid >> 2, t = lid & 3;

    int Nc = Kd / BKC;

    // prologue: stage 0
    {
        uint32_t so = 0;
#pragma unroll
        for (int i = 0; i < 4; i++) {
            cp16(adst[i] + so, asrc[i], asz[i]);
            cp16(bdst[i] + so, bsrc[i], 16);
        }
        cp_commit();
    }

    for (int c = 0; c < Nc; c++) {
        if (c + 1 < Nc) {
            uint32_t so = (uint32_t)(((c + 1) & 1) * STAGE_F) * 4u;
            int k0 = (c + 1) * BKC;
#pragma unroll
            for (int i = 0; i < 4; i++) {
                cp16(adst[i] + so, asrc[i] + k0, asz[i]);
                cp16(bdst[i] + so, bsrc[i] + k0, 16);
            }
            cp_commit();
            cp_wait<1>();
        } else {
            cp_wait<0>();
        }
        __syncthreads();

        const float* As = smf + (c & 1) * STAGE_F;
        const float* Bs = As + 128 * APAD;
#pragma unroll
        for (int ks = 0; ks < 4; ks++) {
            int ko = ks * 8;
            uint32_t a[4][4];
#pragma unroll
            for (int mt = 0; mt < 4; mt++) {
                int r = warpM * 64 + mt * 16 + g;
                a[mt][0] = f2tf(As[r * APAD + ko + t]);
                a[mt][1] = f2tf(As[(r + 8) * APAD + ko + t]);
                a[mt][2] = f2tf(As[r * APAD + ko + t + 4]);
                a[mt][3] = f2tf(As[(r + 8) * APAD + ko + t + 4]);
            }
            uint32_t b[4][2];
#pragma unroll
            for (int nt = 0; nt < 4; nt++) {
                int r = warpN * 32 + nt * 8 + g;
                b[nt][0] = f2tf(Bs[r * APAD + ko + t]);
                b[nt][1] = f2tf(Bs[r * APAD + ko + t + 4]);
            }
#pragma unroll
            for (int mt = 0; mt < 4; mt++)
#pragma unroll
                for (int nt = 0; nt < 4; nt++)
                    mma_tf32(acc[mt * 4 + nt], a[mt], b[nt]);
        }
        __syncthreads();
    }

    // ---- epilogue ----
#pragma unroll
    for (int mt = 0; mt < 4; mt++) {
        int rl0 = warpM * 64 + mt * 16 + g;
        int r0 = tileStart + rl0;
        int r1 = r0 + 8;
        int tok0 = 0, tok1 = 0; float w0 = 0.f, w1 = 0.f;
        if (EPI == 2) {
            tok0 = g_rowtok[r0]; tok1 = g_rowtok[r1];
            w0 = g_roww[r0];     w1 = g_roww[r1];
        }
#pragma unroll
        for (int nt = 0; nt < 4; nt++) {
            float* c = acc[mt * 4 + nt];
            int colL = warpN * 32 + nt * 8 + 2 * t;
            int col = nbase + colL;
            if (EPI == 0) {
                float b0 = par_b[colL], b1 = par_b[colL + 1];
                float s0 = par_sc[colL], s1 = par_sc[colL + 1];
                float h0 = par_sh[colL], h1 = par_sh[colL + 1];
                float2 o0, o1;
                o0.x = fmaf(fmaxf(c[0] + b0, 0.f), s0, h0);
                o0.y = fmaf(fmaxf(c[1] + b1, 0.f), s1, h1);
                o1.x = fmaf(fmaxf(c[2] + b0, 0.f), s0, h0);
                o1.y = fmaf(fmaxf(c[3] + b1, 0.f), s1, h1);
                *(float2*)(out + (size_t)r0 * Hout + col) = o0;
                *(float2*)(out + (size_t)r1 * Hout + col) = o1;
            } else if (EPI == 1) {
                float b0 = par_b[colL], b1 = par_b[colL + 1];
                float2 o0, o1;
                o0.x = 1.f / (1.f + __expf(-(c[0] + b0)));
                o0.y = 1.f / (1.f + __expf(-(c[1] + b1)));
                o1.x = 1.f / (1.f + __expf(-(c[2] + b0)));
                o1.y = 1.f / (1.f + __expf(-(c[3] + b1)));
                *(float2*)(out + (size_t)r0 * Hout + col) = o0;
                *(float2*)(out + (size_t)r1 * Hout + col) = o1;
            } else {
                float b0 = par_b[colL], b1 = par_b[colL + 1];
                if (tok0 >= 0) {
                    float* orow = out + (size_t)tok0 * Hout + col;
                    atomicAdd(&orow[0], w0 * (1.f / (1.f + __expf(-(c[0] + b0)))));
                    atomicAdd(&orow[1], w0 * (1.f / (1.f + __expf(-(c[1] + b1)))));
                }
                if (tok1 >= 0) {
                    float* orow = out + (size_t)tok1 * Hout + col;
                    atomicAdd(&orow[0], w1 * (1.f / (1.f + __expf(-(c[2] + b0)))));
                    atomicAdd(&orow[1], w1 * (1.f / (1.f + __expf(-(c[3] + b1)))));
                }
            }
        }
    }
}

// ---------------- launch ----------------
extern "C" void kernel_launch(void* const* d_in, const int* in_sizes, int n_in,
                              void* d_out, int out_size) {
    (void)in_sizes; (void)n_in; (void)out_size;

    const float* x   = (const float*)d_in[0];
    const float* Wg  = (const float*)d_in[1];
    const float* W1  = (const float*)d_in[2];
    const float* b1  = (const float*)d_in[3];
    const float* g1  = (const float*)d_in[4];
    const float* be1 = (const float*)d_in[5];
    const float* m1  = (const float*)d_in[6];
    const float* v1  = (const float*)d_in[7];
    const float* W2  = (const float*)d_in[8];
    const float* b2  = (const float*)d_in[9];
    const float* g2  = (const float*)d_in[10];
    const float* be2 = (const float*)d_in[11];
    const float* m2  = (const float*)d_in[12];
    const float* v2  = (const float*)d_in[13];
    const float* W3  = (const float*)d_in[14];
    const float* b3  = (const float*)d_in[15];
    const float* sW1 = (const float*)d_in[16];
    const float* sb1 = (const float*)d_in[17];
    const float* sg1 = (const float*)d_in[18];
    const float* sbe1= (const float*)d_in[19];
    const float* sm1 = (const float*)d_in[20];
    const float* sv1 = (const float*)d_in[21];
    const float* sW2 = (const float*)d_in[22];
    const float* sb2 = (const float*)d_in[23];
    const float* sg2 = (const float*)d_in[24];
    const float* sbe2= (const float*)d_in[25];
    const float* sm2 = (const float*)d_in[26];
    const float* sv2 = (const float*)d_in[27];
    const float* sW3 = (const float*)d_in[28];
    const float* sb3 = (const float*)d_in[29];
    float* out = (float*)d_out;

    float* bufA; float* bufB; int* off;
    cudaGetSymbolAddress((void**)&bufA, g_bufA);
    cudaGetSymbolAddress((void**)&bufB, g_bufB);
    cudaGetSymbolAddress((void**)&off,  g_off);

    cudaFuncSetAttribute(gemm_tc<0, true>,  cudaFuncAttributeMaxDynamicSharedMemorySize, SMEM_BYTES);
    cudaFuncSetAttribute(gemm_tc<0, false>, cudaFuncAttributeMaxDynamicSharedMemorySize, SMEM_BYTES);
    cudaFuncSetAttribute(gemm_tc<1, false>, cudaFuncAttributeMaxDynamicSharedMemorySize, SMEM_BYTES);
    cudaFuncSetAttribute(gemm_tc<2, false>, cudaFuncAttributeMaxDynamicSharedMemorySize, SMEM_BYTES);

    // routing
    k_init<<<(ROWS_MAX + 255) / 256, 256>>>();
    k_gate<<<N_TOK / 8, 256>>>(x, Wg);
    k_offsets<<<1, 32>>>();
    k_scatter<<<(N_TOK + 255) / 256, 256>>>();

    // shared expert: x -> bufA -> bufB -> out (plain store initializes d_out)
    gemm_tc<0, false><<<dim3(HID / BN, N_TOK / BM), 256, SMEM_BYTES>>>(
        x, sW1, sb1, sg1, sbe1, sm1, sv1, bufA, DIM, HID, 0, 0, nullptr);
    gemm_tc<0, false><<<dim3(HID / BN, N_TOK / BM), 256, SMEM_BYTES>>>(
        bufA, sW2, sb2, sg2, sbe2, sm2, sv2, bufB, HID, HID, 0, 0, nullptr);
    gemm_tc<1, false><<<dim3(OUTD / BN, N_TOK / BM), 256, SMEM_BYTES>>>(
        bufB, sW3, sb3, nullptr, nullptr, nullptr, nullptr, out, HID, OUTD, 0, 0, nullptr);

    // routed experts (top-2 compacted): gather -> bufA -> bufB -> out (+=)
    gemm_tc<0, true><<<dim3(HID / BN, ROWS_MAX / BM), 256, SMEM_BYTES>>>(
        x, W1, b1, g1, be1, m1, v1, bufA, DIM, HID, (long)HID * DIM, HID, off);
    gemm_tc<0, false><<<dim3(HID / BN, ROWS_MAX / BM), 256, SMEM_BYTES>>>(
        bufA, W2, b2, g2, be2, m2, v2, bufB, HID, HID, (long)HID * HID, HID, off);
    gemm_tc<2, false><<<dim3(OUTD / BN, ROWS_MAX / BM), 256, SMEM_BYTES>>>(
        bufB, W3, b3, nullptr, nullptr, nullptr, nullptr, out, HID, OUTD, (long)OUTD * HID, OUTD, off);
}